// round 1
// baseline (speedup 1.0000x reference)
#include <cuda_runtime.h>

typedef unsigned long long u64;

#define HID 10
static __device__ __constant__ const float NU_F = 0.0031830988618379067f; // 0.01/pi  (placeholder removed below)

struct Params {
    const float* W[9];
    const float* b[9];
};

// Shared weight stash: weights duplicated into both halves of a float2 so a
// single LDS.64 feeds the packed f32x2 FMA for both jet streams.
struct SW {
    float2 W1[2][HID];        // layer 1 (2 -> 10), duplicated
    float2 Wh[7][HID][HID];   // layers 2..8 (10 -> 10), duplicated
    float2 W9[HID];           // layer 9 (10 -> 1), duplicated
    float  b1[HID];
    float  bh[7][HID];
    float  b9;
};

__device__ __forceinline__ u64 pk2(float lo, float hi) {
    u64 r; asm("mov.b64 %0,{%1,%2};" : "=l"(r) : "f"(lo), "f"(hi)); return r;
}
__device__ __forceinline__ void upk2(u64 v, float& lo, float& hi) {
    asm("mov.b64 {%0,%1},%2;" : "=f"(lo), "=f"(hi) : "l"(v));
}
__device__ __forceinline__ u64 fma2(u64 a, u64 b, u64 c) {
    u64 d; asm("fma.rn.f32x2 %0,%1,%2,%3;" : "=l"(d) : "l"(a), "l"(b), "l"(c)); return d;
}
__device__ __forceinline__ u64 mul2(u64 a, u64 b) {
    u64 d; asm("mul.rn.f32x2 %0,%1,%2;" : "=l"(d) : "l"(a), "l"(b)); return d;
}

// Accurate-enough fast tanh: t = 1 - 2/(exp(2z)+1).  Clamp keeps exp finite;
// beyond |z|=15 tanh is saturated to < 1e-13 of +-1.
__device__ __forceinline__ float tanh_fast(float z) {
    float zc = fminf(fmaxf(z, -15.0f), 15.0f);
    float e  = __expf(2.0f * zc);
    return 1.0f - __fdividef(2.0f, e + 1.0f);
}

__device__ __forceinline__ void load_weights(SW& s, const Params& p) {
    int t = threadIdx.x;
    for (int i = t; i < 2 * HID; i += blockDim.x) {
        float w = p.W[0][i];
        s.W1[i / HID][i % HID] = make_float2(w, w);
    }
    for (int l = 0; l < 7; l++)
        for (int i = t; i < HID * HID; i += blockDim.x) {
            float w = p.W[l + 1][i];
            s.Wh[l][i / HID][i % HID] = make_float2(w, w);
        }
    for (int i = t; i < HID; i += blockDim.x) {
        float w = p.W[8][i];
        s.W9[i] = make_float2(w, w);
    }
    for (int i = t; i < HID; i += blockDim.x) s.b1[i] = p.b[0][i];
    for (int l = 0; l < 7; l++)
        for (int i = t; i < HID; i += blockDim.x) s.bh[l][i] = p.b[l + 1][i];
    if (t == 0) s.b9 = p.b[8][0];
}

// ---------------------------------------------------------------------------
// Jet kernel: per point propagate (u, u_xx) packed in P and (u_x, u_t) packed
// in Q through the MLP via 2nd-order forward-mode AD.
//   linear:  zP = W^T P + (b,0);  zQ = W^T Q
//   tanh:    t = tanh(z), s = 1 - t^2
//            P' = (t,  s*zxx - 2*t*s*zx^2),  Q' = s * zQ
// ---------------------------------------------------------------------------
__global__ void __launch_bounds__(256, 2)
jet_kernel(const float* __restrict__ Xf, Params p, float* __restrict__ out,
           int nf, int offF, int offUX, int offUXX)
{
    __shared__ SW s;
    load_weights(s, p);
    __syncthreads();

    int i = blockIdx.x * blockDim.x + threadIdx.x;
    if (i >= nf) return;

    float x  = Xf[2 * i + 0];
    float tt = Xf[2 * i + 1];

    u64 P[HID], Q[HID];

    // Layer 1: input (x,t); a_x=(1,0), a_t=(0,1), a_xx=0.
    #pragma unroll
    for (int j = 0; j < HID; j++) {
        float w0 = s.W1[0][j].x;
        float w1 = s.W1[1][j].x;
        float z  = fmaf(x, w0, fmaf(tt, w1, s.b1[j]));
        float t  = tanh_fast(z);
        float sv = fmaf(-t, t, 1.0f);
        float hxx = -2.0f * t * sv * w0 * w0;   // zxx = 0 here, zx = w0
        P[j] = pk2(t, hxx);
        Q[j] = pk2(sv * w0, sv * w1);
    }

    // Hidden layers 2..8
    #pragma unroll 1
    for (int l = 0; l < 7; l++) {
        u64 zP[HID], zQ[HID];
        #pragma unroll
        for (int j = 0; j < HID; j++) {
            zP[j] = pk2(s.bh[l][j], 0.0f);
            zQ[j] = 0ull;
        }
        #pragma unroll
        for (int k = 0; k < HID; k++) {
            u64 Pk = P[k], Qk = Q[k];
            #pragma unroll
            for (int j = 0; j < HID; j++) {
                u64 w = *reinterpret_cast<const u64*>(&s.Wh[l][k][j]);
                zP[j] = fma2(Pk, w, zP[j]);
                zQ[j] = fma2(Qk, w, zQ[j]);
            }
        }
        #pragma unroll
        for (int j = 0; j < HID; j++) {
            float z, zxx;  upk2(zP[j], z, zxx);
            float zx, zt;  upk2(zQ[j], zx, zt);
            (void)zt;
            float t  = tanh_fast(z);
            float sv = fmaf(-t, t, 1.0f);
            float hxx = fmaf(sv, zxx, -2.0f * t * sv * zx * zx);
            P[j] = pk2(t, hxx);
            Q[j] = mul2(zQ[j], pk2(sv, sv));
        }
    }

    // Output layer (10 -> 1), linear.
    u64 aP = pk2(s.b9, 0.0f);
    u64 aQ = 0ull;
    #pragma unroll
    for (int k = 0; k < HID; k++) {
        u64 w = *reinterpret_cast<const u64*>(&s.W9[k]);
        aP = fma2(P[k], w, aP);
        aQ = fma2(Q[k], w, aQ);
    }
    float u, uxx;  upk2(aP, u, uxx);
    float ux, ut;  upk2(aQ, ux, ut);

    const float nu = 0.0031830988618379067f;   // 0.01 / pi
    float f = fmaf(u, ux, fmaf(-nu, uxx, ut)); // u_t + u*u_x - nu*u_xx

    out[i]          = u;
    out[offF + i]   = f;
    out[offUX + i]  = ux;
    out[offUXX + i] = uxx;
}

// ---------------------------------------------------------------------------
// Forward-only kernel for the three boundary/initial batches (49,152 points).
// ---------------------------------------------------------------------------
__global__ void __launch_bounds__(256)
fwd_kernel(const float* __restrict__ p0, const float* __restrict__ p1,
           const float* __restrict__ p2, Params p, float* __restrict__ out,
           int n0, int nb, int off0)
{
    __shared__ SW s;
    load_weights(s, p);
    __syncthreads();

    int i = blockIdx.x * blockDim.x + threadIdx.x;
    int total = n0 + 2 * nb;
    if (i >= total) return;

    const float* src;
    int loc, off;
    if (i < n0)           { src = p0; loc = i;            off = off0; }
    else if (i < n0 + nb) { src = p1; loc = i - n0;       off = off0 + n0; }
    else                  { src = p2; loc = i - n0 - nb;  off = off0 + n0 + nb; }

    float x  = src[2 * loc + 0];
    float tt = src[2 * loc + 1];

    float h[HID];
    #pragma unroll
    for (int j = 0; j < HID; j++)
        h[j] = tanh_fast(fmaf(x, s.W1[0][j].x, fmaf(tt, s.W1[1][j].x, s.b1[j])));

    #pragma unroll 1
    for (int l = 0; l < 7; l++) {
        float z[HID];
        #pragma unroll
        for (int j = 0; j < HID; j++) z[j] = s.bh[l][j];
        #pragma unroll
        for (int k = 0; k < HID; k++) {
            float hk = h[k];
            #pragma unroll
            for (int j = 0; j < HID; j++)
                z[j] = fmaf(hk, s.Wh[l][k][j].x, z[j]);
        }
        #pragma unroll
        for (int j = 0; j < HID; j++) h[j] = tanh_fast(z[j]);
    }

    float u = s.b9;
    #pragma unroll
    for (int k = 0; k < HID; k++) u = fmaf(h[k], s.W9[k].x, u);

    out[off + loc] = u;
}

// ---------------------------------------------------------------------------
// Output layout (reference tuple order, concatenated):
//   [0, nf)                      u_pred_f
//   [nf, nf+n0)                  u_pred_0
//   [nf+n0, nf+n0+nb)            u_pred_b_left
//   [nf+n0+nb, nf+n0+2nb)        u_pred_b_right
//   [.., +nf)                    f
//   [.., +nf)                    u_x
//   [.., +nf)                    u_xx
// ---------------------------------------------------------------------------
extern "C" void kernel_launch(void* const* d_in, const int* in_sizes, int n_in,
                              void* d_out, int out_size)
{
    Params p;
    for (int i = 0; i < 9; i++) {
        p.W[i] = (const float*)d_in[4 + 2 * i];
        p.b[i] = (const float*)d_in[5 + 2 * i];
    }
    const float* Xf = (const float*)d_in[0];
    const float* x0 = (const float*)d_in[1];
    const float* xl = (const float*)d_in[2];
    const float* xr = (const float*)d_in[3];

    int nf = in_sizes[0] / 2;
    int n0 = in_sizes[1] / 2;
    int nb = in_sizes[2] / 2;

    float* out = (float*)d_out;

    int off0   = nf;
    int offF   = nf + n0 + 2 * nb;
    int offUX  = offF + nf;
    int offUXX = offUX + nf;

    jet_kernel<<<(nf + 255) / 256, 256>>>(Xf, p, out, nf, offF, offUX, offUXX);

    int total = n0 + 2 * nb;
    fwd_kernel<<<(total + 255) / 256, 256>>>(x0, xl, xr, p, out, n0, nb, off0);
}